// round 13
// baseline (speedup 1.0000x reference)
#include <cuda_runtime.h>
#include <cuda_bf16.h>
#include <math.h>
#include <stdint.h>

#define NB 64
#define NT 512
#define ND 1024
#define TV 506
#define NMARG 5
#define TEMP_INV 10.0f
#define NPAIR 10

// scratch (allocation-free rule: __device__ globals)
__device__ __nv_bfloat16 g_feat[(size_t)NB * NT * ND];   // 64 MB normalized bf16
__device__ float    g_d1[NB * NT];
__device__ float    g_d2[NB * NT];
__device__ float    g_pm[NB * NPAIR * 128];
__device__ float    g_pz[NB * NPAIR * 128];
__device__ double   g_acc;
__device__ unsigned g_done = 0;

// pair p -> (t-tile k, s-tile j), 128x128 tiles, j >= k (upper wedge)
__constant__ int c_tk[NPAIR] = {0,0,0,0, 1,1,1, 2,2, 3};
__constant__ int c_sj[NPAIR] = {0,1,2,3, 1,2,3, 2,3, 3};

__device__ __forceinline__ uint32_t smem_u32(const void* p) {
    uint32_t a;
    asm("{ .reg .u64 t; cvta.to.shared.u64 t, %1; cvt.u32.u64 %0, t; }"
        : "=r"(a) : "l"(p));
    return a;
}
__device__ __forceinline__ uint32_t swz64(uint32_t off) {
    return off ^ ((off >> 3) & 0x30);
}
__device__ __forceinline__ void cp16(uint32_t sdst, const void* gsrc) {
    asm volatile("cp.async.cg.shared.global [%0], [%1], 16;"
                 :: "r"(sdst), "l"(gsrc));
}
#define CP_COMMIT() asm volatile("cp.async.commit_group;" ::: "memory")
#define CP_WAIT1()  asm volatile("cp.async.wait_group 1;" ::: "memory")
#define CP_WAIT0()  asm volatile("cp.async.wait_group 0;" ::: "memory")

// ---------------------------------------------------------------- kernels
// normalize row + write bf16 feats; block 0 also zeroes the accumulator.
__global__ void k_norm(const float* __restrict__ h) {
    int bt = blockIdx.x;
    int tid = threadIdx.x;
    if (bt == 0 && tid == 0) { g_acc = 0.0; g_done = 0; }
    const float4* p = (const float4*)(h + (size_t)bt * ND);
    float4 v0 = p[tid];
    float4 v1 = p[tid + 128];
    float ss = v0.x*v0.x + v0.y*v0.y + v0.z*v0.z + v0.w*v0.w
             + v1.x*v1.x + v1.y*v1.y + v1.z*v1.z + v1.w*v1.w;
#pragma unroll
    for (int o = 16; o; o >>= 1) ss += __shfl_xor_sync(0xffffffffu, ss, o);
    __shared__ float sm[4];
    __shared__ float s_rn;
    if ((tid & 31) == 0) sm[tid >> 5] = ss;
    __syncthreads();
    if (tid == 0) {
        float tot = sm[0] + sm[1] + sm[2] + sm[3];
        s_rn = 1.0f / fmaxf(sqrtf(tot), 1e-12f);
    }
    __syncthreads();
    float r = s_rn;
    __nv_bfloat162* out = (__nv_bfloat162*)(g_feat + (size_t)bt * ND);
    out[2 * tid + 0]       = __floats2bfloat162_rn(v0.x * r, v0.y * r);
    out[2 * tid + 1]       = __floats2bfloat162_rn(v0.z * r, v0.w * r);
    out[256 + 2 * tid + 0] = __floats2bfloat162_rn(v1.x * r, v1.y * r);
    out[256 + 2 * tid + 1] = __floats2bfloat162_rn(v1.z * r, v1.w * r);
}

// -------------------------------------------------------- pipelined HMMA
// 128x128 tile per block; K in 32 chunks of 32 elems (64B rows, SW64),
// cp.async 3-stage ring, ONE __syncthreads per stage.
// Diagonal tiles: warp tiles fully under the mask skip ldmatrix+mma entirely.
#define STGB 16384   // bytes per stage (A 8KB @ +0, B 8KB @ +8192)

__device__ __forceinline__ void stage_issue(
    uint32_t sPipe, int buf, const char* fA, const char* fB, int st, int tid) {
    int kb = st * 64;
    uint32_t sb = sPipe + buf * STGB;
#pragma unroll
    for (int i = 0; i < 2; i++) {
        int l = tid + i * 256;
        int row = l >> 2, u = l & 3;
        cp16(sb + swz64(row * 64 + u * 16),
             fA + (size_t)row * 2048 + kb + u * 16);
    }
#pragma unroll
    for (int i = 0; i < 2; i++) {
        int l = tid + i * 256;
        int row = l >> 2, u = l & 3;
        cp16(sb + 8192 + swz64(row * 64 + u * 16),
             fB + (size_t)row * 2048 + kb + u * 16);
    }
}

__device__ __forceinline__ void stage_compute(
    uint32_t sPipe, int buf, int lane, int warp_m, int warp_n,
    float (*acc)[8][4]) {
    uint32_t sAu = sPipe + buf * STGB;
    uint32_t sBu = sAu + 8192;
#pragma unroll
    for (int ks = 0; ks < 2; ks++) {
        uint32_t a[2][4];
#pragma unroll
        for (int mf = 0; mf < 2; mf++) {
            int row = warp_m * 32 + mf * 16 + (lane & 15);
            int col = ks * 32 + (lane >> 4) * 16;
            uint32_t addr = sAu + swz64(row * 64 + col);
            asm volatile(
                "ldmatrix.sync.aligned.m8n8.x4.shared.b16 {%0,%1,%2,%3}, [%4];"
                : "=r"(a[mf][0]), "=r"(a[mf][1]), "=r"(a[mf][2]), "=r"(a[mf][3])
                : "r"(addr));
        }
        uint32_t bfr[4][4];
#pragma unroll
        for (int g = 0; g < 4; g++) {
            int row = warp_n * 64 + g * 16 + (lane & 7) + ((lane >> 4) << 3);
            int col = ks * 32 + ((lane >> 3) & 1) * 16;
            uint32_t addr = sBu + swz64(row * 64 + col);
            asm volatile(
                "ldmatrix.sync.aligned.m8n8.x4.shared.b16 {%0,%1,%2,%3}, [%4];"
                : "=r"(bfr[g][0]), "=r"(bfr[g][1]), "=r"(bfr[g][2]), "=r"(bfr[g][3])
                : "r"(addr));
        }
#pragma unroll
        for (int mf = 0; mf < 2; mf++)
#pragma unroll
            for (int nf = 0; nf < 8; nf++) {
                uint32_t b0 = bfr[nf >> 1][(nf & 1) * 2];
                uint32_t b1 = bfr[nf >> 1][(nf & 1) * 2 + 1];
                asm volatile(
                    "mma.sync.aligned.m16n8k16.row.col.f32.bf16.bf16.f32 "
                    "{%0,%1,%2,%3}, {%4,%5,%6,%7}, {%8,%9}, {%0,%1,%2,%3};"
                    : "+f"(acc[mf][nf][0]), "+f"(acc[mf][nf][1]),
                      "+f"(acc[mf][nf][2]), "+f"(acc[mf][nf][3])
                    : "r"(a[mf][0]), "r"(a[mf][1]), "r"(a[mf][2]), "r"(a[mf][3]),
                      "r"(b0), "r"(b1));
            }
    }
}

__global__ void __launch_bounds__(256, 2) k_mma() {
    __shared__ __align__(128) char s_pipe[3][STGB];  // 49152B = static smem cap

    int tid = threadIdx.x;
    int lane = tid & 31;
    int wid = tid >> 5;
    int warp_m = wid >> 1;
    int warp_n = wid & 1;
    int p = blockIdx.x, b = blockIdx.y;
    int t0 = c_tk[p] * 128, s0 = c_sj[p] * 128;

    // fully-masked warp tile on diagonal blocks: rows>=64, cols<64 -> all s<t+5
    bool active = !((t0 == s0) && (warp_n == 0) && (warp_m >= 2));

    const char* fb = (const char*)(g_feat + (size_t)b * NT * ND);
    const char* fA = fb + (size_t)t0 * (ND * 2);
    const char* fB = fb + (size_t)s0 * (ND * 2);

    float acc[2][8][4];
#pragma unroll
    for (int i = 0; i < 2; i++)
#pragma unroll
        for (int j = 0; j < 8; j++)
#pragma unroll
            for (int e = 0; e < 4; e++) acc[i][j][e] = 0.f;

    uint32_t sPipe = smem_u32(s_pipe);

    stage_issue(sPipe, 0, fA, fB, 0, tid); CP_COMMIT();
    stage_issue(sPipe, 1, fA, fB, 1, tid); CP_COMMIT();

    int buf = 0, nxt = 2;
#pragma unroll 1
    for (int st = 0; st < 32; st++) {
        if (st < 30) {
            CP_WAIT1();
            __syncthreads();
            stage_issue(sPipe, nxt, fA, fB, st + 2, tid);
            CP_COMMIT();
        } else {
            CP_WAIT0();
            __syncthreads();
        }
        if (active) stage_compute(sPipe, buf, lane, warp_m, warp_n, acc);
        buf = (buf == 2) ? 0 : buf + 1;
        nxt = (nxt == 2) ? 0 : nxt + 1;
    }

    // epilogue: masked streaming logsumexp + harvest d1/d2 from accumulators
    __syncthreads();
    float* red_m = (float*)&s_pipe[0][0];      // [2][128]
    float* red_z = red_m + 256;                // [2][128]
    int q = lane >> 2, c2 = lane & 3;
#pragma unroll
    for (int mf = 0; mf < 2; mf++)
#pragma unroll
        for (int hf = 0; hf < 2; hf++) {
            int row = warp_m * 32 + mf * 16 + hf * 8 + q;
            int tg = t0 + row;
            float m = -1e30f, z = 0.f;
#pragma unroll
            for (int nf = 0; nf < 8; nf++)
#pragma unroll
                for (int e = 0; e < 2; e++) {
                    int sg = s0 + warp_n * 64 + nf * 8 + c2 * 2 + e;
                    float raw = acc[mf][nf][hf * 2 + e];
                    int d = sg - tg;
                    // d1/d2 harvest: each (t,t+1)/(t,t+2) lives in exactly one block
                    if (d == 1) g_d1[b * NT + tg] = raw;
                    if (d == 2) g_d2[b * NT + tg] = raw;
                    if (tg < TV && d >= NMARG) {
                        float v = raw * TEMP_INV;
                        if (v > m) { z = z * __expf(m - v) + 1.f; m = v; }
                        else        z += __expf(v - m);
                    }
                }
#pragma unroll
            for (int off = 1; off <= 2; off <<= 1) {
                float m2 = __shfl_xor_sync(0xffffffffu, m, off);
                float z2 = __shfl_xor_sync(0xffffffffu, z, off);
                float mm = fmaxf(m, m2);
                z = z * __expf(m - mm) + z2 * __expf(m2 - mm);
                m = mm;
            }
            if (c2 == 0) {
                red_m[warp_n * 128 + row] = m;
                red_z[warp_n * 128 + row] = z;
            }
        }
    __syncthreads();
    if (tid < 128) {
        float m0 = red_m[tid],       z0 = red_z[tid];
        float m1 = red_m[128 + tid], z1 = red_z[128 + tid];
        float mm = fmaxf(m0, m1);
        float zz = z0 * __expf(m0 - mm) + z1 * __expf(m1 - mm);
        g_pm[(b * NPAIR + p) * 128 + tid] = mm;
        g_pz[(b * NPAIR + p) * 128 + tid] = zz;
    }
}

// merge tile partials per (b,t-group), build pos from d1/d2, accumulate loss;
// last block writes the final scalar.
__global__ void k_reduce(float* out) {
    int b = blockIdx.x;
    int k = blockIdx.y;          // t-group 0..3
    int t = k * 128 + threadIdx.x;   // 128 threads
    float loss = 0.f;
    if (t < TV) {
        const int ps_[5] = {0, 4, 7, 9, 10};
        float m = -1e30f, z = 0.f;
        for (int p = ps_[k]; p < ps_[k + 1]; p++) {
            float mp = g_pm[(b * NPAIR + p) * 128 + threadIdx.x];
            float zp = g_pz[(b * NPAIR + p) * 128 + threadIdx.x];
            float mm = fmaxf(m, mp);
            z = z * expf(m - mm) + zp * expf(mp - mm);
            m = mm;
        }
        float s = g_d1[b * NT + t] + g_d2[b * NT + t];
        int cnt = 2;
        if (t >= 1) { s += g_d1[b * NT + t - 1]; cnt++; }
        if (t >= 2) { s += g_d2[b * NT + t - 2]; cnt++; }
        float pscore = s / (float)cnt * TEMP_INV;
        float mm = fmaxf(m, pscore);
        float zz = z * expf(m - mm) + expf(pscore - mm);
        loss = mm + logf(zz) - pscore;
    }
#pragma unroll
    for (int o = 16; o; o >>= 1) loss += __shfl_xor_sync(0xffffffffu, loss, o);
    __shared__ float sm[4];
    if ((threadIdx.x & 31) == 0) sm[threadIdx.x >> 5] = loss;
    __syncthreads();
    if (threadIdx.x == 0) {
        float tot = sm[0] + sm[1] + sm[2] + sm[3];
        atomicAdd(&g_acc, (double)tot);
        __threadfence();
        unsigned v = atomicAdd(&g_done, 1u);
        if (v == NB * 4 - 1) {
            out[0] = (float)(g_acc / (double)((size_t)NB * TV));
            g_done = 0;      // reset for next graph replay
        }
    }
}

// ---------------------------------------------------------------- launch
extern "C" void kernel_launch(void* const* d_in, const int* in_sizes, int n_in,
                              void* d_out, int out_size) {
    const float* h = (const float*)d_in[0];
    (void)in_sizes; (void)n_in; (void)out_size;

    k_norm<<<NB * NT, 128>>>(h);
    k_mma<<<dim3(NPAIR, NB), 256>>>();
    k_reduce<<<dim3(NB, 4), 128>>>((float*)d_out);
}

// round 14
// speedup vs baseline: 1.4846x; 1.4846x over previous
#include <cuda_runtime.h>
#include <cuda_bf16.h>
#include <math.h>
#include <stdint.h>

#define NB 64
#define NT 512
#define ND 1024
#define TV 506
#define NMARG 5
#define TEMP_INV 10.0f
#define NPAIR 10

// scratch (allocation-free rule: __device__ globals)
__device__ __nv_bfloat16 g_feat[(size_t)NB * NT * ND];   // 64 MB normalized bf16
__device__ float    g_d1[NB * NT];
__device__ float    g_d2[NB * NT];
__device__ float    g_pm[NB * NPAIR * 128];
__device__ float    g_pz[NB * NPAIR * 128];
__device__ double   g_acc;
__device__ unsigned g_done = 0;

// pair p -> (t-tile k, s-tile j), 128x128 tiles, j >= k (upper wedge)
__constant__ int c_tk[NPAIR] = {0,0,0,0, 1,1,1, 2,2, 3};
__constant__ int c_sj[NPAIR] = {0,1,2,3, 1,2,3, 2,3, 3};

__device__ __forceinline__ uint32_t smem_u32(const void* p) {
    uint32_t a;
    asm("{ .reg .u64 t; cvta.to.shared.u64 t, %1; cvt.u32.u64 %0, t; }"
        : "=r"(a) : "l"(p));
    return a;
}
__device__ __forceinline__ uint32_t swz64(uint32_t off) {
    return off ^ ((off >> 3) & 0x30);
}
__device__ __forceinline__ void cp16(uint32_t sdst, const void* gsrc) {
    asm volatile("cp.async.cg.shared.global [%0], [%1], 16;"
                 :: "r"(sdst), "l"(gsrc));
}
#define CP_COMMIT() asm volatile("cp.async.commit_group;" ::: "memory")
#define CP_WAIT1()  asm volatile("cp.async.wait_group 1;" ::: "memory")
#define CP_WAIT0()  asm volatile("cp.async.wait_group 0;" ::: "memory")

// ---------------------------------------------------------------- kernels
// normalize row + write bf16 feats; block 0 also zeroes the accumulator.
__global__ void k_norm(const float* __restrict__ h) {
    int bt = blockIdx.x;
    int tid = threadIdx.x;
    if (bt == 0 && tid == 0) { g_acc = 0.0; g_done = 0; }
    const float4* p = (const float4*)(h + (size_t)bt * ND);
    float4 v0 = p[tid];
    float4 v1 = p[tid + 128];
    float ss = v0.x*v0.x + v0.y*v0.y + v0.z*v0.z + v0.w*v0.w
             + v1.x*v1.x + v1.y*v1.y + v1.z*v1.z + v1.w*v1.w;
#pragma unroll
    for (int o = 16; o; o >>= 1) ss += __shfl_xor_sync(0xffffffffu, ss, o);
    __shared__ float sm[4];
    __shared__ float s_rn;
    if ((tid & 31) == 0) sm[tid >> 5] = ss;
    __syncthreads();
    if (tid == 0) {
        float tot = sm[0] + sm[1] + sm[2] + sm[3];
        s_rn = 1.0f / fmaxf(sqrtf(tot), 1e-12f);
    }
    __syncthreads();
    float r = s_rn;
    __nv_bfloat162* out = (__nv_bfloat162*)(g_feat + (size_t)bt * ND);
    out[2 * tid + 0]       = __floats2bfloat162_rn(v0.x * r, v0.y * r);
    out[2 * tid + 1]       = __floats2bfloat162_rn(v0.z * r, v0.w * r);
    out[256 + 2 * tid + 0] = __floats2bfloat162_rn(v1.x * r, v1.y * r);
    out[256 + 2 * tid + 1] = __floats2bfloat162_rn(v1.z * r, v1.w * r);
}

// -------------------------------------------------------- pipelined HMMA
// 128x128 tile per block; K in 32 chunks of 32 elems (64B rows, SW64),
// cp.async 3-stage ring, ONE __syncthreads per stage.
// Epilogue also harvests d1/d2 (pos-score dots) straight from the accumulators.
#define STGB 16384   // bytes per stage (A 8KB @ +0, B 8KB @ +8192)

__device__ __forceinline__ void stage_issue(
    uint32_t sPipe, int buf, const char* fA, const char* fB, int st, int tid) {
    int kb = st * 64;
    uint32_t sb = sPipe + buf * STGB;
#pragma unroll
    for (int i = 0; i < 2; i++) {
        int l = tid + i * 256;
        int row = l >> 2, u = l & 3;
        cp16(sb + swz64(row * 64 + u * 16),
             fA + (size_t)row * 2048 + kb + u * 16);
    }
#pragma unroll
    for (int i = 0; i < 2; i++) {
        int l = tid + i * 256;
        int row = l >> 2, u = l & 3;
        cp16(sb + 8192 + swz64(row * 64 + u * 16),
             fB + (size_t)row * 2048 + kb + u * 16);
    }
}

__device__ __forceinline__ void stage_compute(
    uint32_t sPipe, int buf, int lane, int warp_m, int warp_n,
    float (*acc)[8][4]) {
    uint32_t sAu = sPipe + buf * STGB;
    uint32_t sBu = sAu + 8192;
#pragma unroll
    for (int ks = 0; ks < 2; ks++) {
        uint32_t a[2][4];
#pragma unroll
        for (int mf = 0; mf < 2; mf++) {
            int row = warp_m * 32 + mf * 16 + (lane & 15);
            int col = ks * 32 + (lane >> 4) * 16;
            uint32_t addr = sAu + swz64(row * 64 + col);
            asm volatile(
                "ldmatrix.sync.aligned.m8n8.x4.shared.b16 {%0,%1,%2,%3}, [%4];"
                : "=r"(a[mf][0]), "=r"(a[mf][1]), "=r"(a[mf][2]), "=r"(a[mf][3])
                : "r"(addr));
        }
        uint32_t bfr[4][4];
#pragma unroll
        for (int g = 0; g < 4; g++) {
            int row = warp_n * 64 + g * 16 + (lane & 7) + ((lane >> 4) << 3);
            int col = ks * 32 + ((lane >> 3) & 1) * 16;
            uint32_t addr = sBu + swz64(row * 64 + col);
            asm volatile(
                "ldmatrix.sync.aligned.m8n8.x4.shared.b16 {%0,%1,%2,%3}, [%4];"
                : "=r"(bfr[g][0]), "=r"(bfr[g][1]), "=r"(bfr[g][2]), "=r"(bfr[g][3])
                : "r"(addr));
        }
#pragma unroll
        for (int mf = 0; mf < 2; mf++)
#pragma unroll
            for (int nf = 0; nf < 8; nf++) {
                uint32_t b0 = bfr[nf >> 1][(nf & 1) * 2];
                uint32_t b1 = bfr[nf >> 1][(nf & 1) * 2 + 1];
                asm volatile(
                    "mma.sync.aligned.m16n8k16.row.col.f32.bf16.bf16.f32 "
                    "{%0,%1,%2,%3}, {%4,%5,%6,%7}, {%8,%9}, {%0,%1,%2,%3};"
                    : "+f"(acc[mf][nf][0]), "+f"(acc[mf][nf][1]),
                      "+f"(acc[mf][nf][2]), "+f"(acc[mf][nf][3])
                    : "r"(a[mf][0]), "r"(a[mf][1]), "r"(a[mf][2]), "r"(a[mf][3]),
                      "r"(b0), "r"(b1));
            }
    }
}

__global__ void __launch_bounds__(256, 2) k_mma() {
    __shared__ __align__(128) char s_pipe[3][STGB];  // 49152B = static smem cap

    int tid = threadIdx.x;
    int lane = tid & 31;
    int wid = tid >> 5;
    int warp_m = wid >> 1;
    int warp_n = wid & 1;
    int p = blockIdx.x, b = blockIdx.y;
    int t0 = c_tk[p] * 128, s0 = c_sj[p] * 128;

    const char* fb = (const char*)(g_feat + (size_t)b * NT * ND);
    const char* fA = fb + (size_t)t0 * (ND * 2);
    const char* fB = fb + (size_t)s0 * (ND * 2);

    float acc[2][8][4];
#pragma unroll
    for (int i = 0; i < 2; i++)
#pragma unroll
        for (int j = 0; j < 8; j++)
#pragma unroll
            for (int e = 0; e < 4; e++) acc[i][j][e] = 0.f;

    uint32_t sPipe = smem_u32(s_pipe);

    stage_issue(sPipe, 0, fA, fB, 0, tid); CP_COMMIT();
    stage_issue(sPipe, 1, fA, fB, 1, tid); CP_COMMIT();

    int buf = 0, nxt = 2;
#pragma unroll 1
    for (int st = 0; st < 32; st++) {
        if (st < 30) {
            CP_WAIT1();
            __syncthreads();
            stage_issue(sPipe, nxt, fA, fB, st + 2, tid);
            CP_COMMIT();
        } else {
            CP_WAIT0();
            __syncthreads();
        }
        stage_compute(sPipe, buf, lane, warp_m, warp_n, acc);
        buf = (buf == 2) ? 0 : buf + 1;
        nxt = (nxt == 2) ? 0 : nxt + 1;
    }

    // epilogue: masked streaming logsumexp + harvest d1/d2 from accumulators
    __syncthreads();
    float* red_m = (float*)&s_pipe[0][0];      // [2][128]
    float* red_z = red_m + 256;                // [2][128]
    int q = lane >> 2, c2 = lane & 3;
#pragma unroll
    for (int mf = 0; mf < 2; mf++)
#pragma unroll
        for (int hf = 0; hf < 2; hf++) {
            int row = warp_m * 32 + mf * 16 + hf * 8 + q;
            int tg = t0 + row;
            float m = -1e30f, z = 0.f;
#pragma unroll
            for (int nf = 0; nf < 8; nf++)
#pragma unroll
                for (int e = 0; e < 2; e++) {
                    int sg = s0 + warp_n * 64 + nf * 8 + c2 * 2 + e;
                    float raw = acc[mf][nf][hf * 2 + e];
                    int d = sg - tg;
                    // d1/d2 harvest: each (t,t+1)/(t,t+2) lives in exactly one block
                    if (d == 1) g_d1[b * NT + tg] = raw;
                    if (d == 2) g_d2[b * NT + tg] = raw;
                    if (tg < TV && d >= NMARG) {
                        float v = raw * TEMP_INV;
                        if (v > m) { z = z * __expf(m - v) + 1.f; m = v; }
                        else        z += __expf(v - m);
                    }
                }
#pragma unroll
            for (int off = 1; off <= 2; off <<= 1) {
                float m2 = __shfl_xor_sync(0xffffffffu, m, off);
                float z2 = __shfl_xor_sync(0xffffffffu, z, off);
                float mm = fmaxf(m, m2);
                z = z * __expf(m - mm) + z2 * __expf(m2 - mm);
                m = mm;
            }
            if (c2 == 0) {
                red_m[warp_n * 128 + row] = m;
                red_z[warp_n * 128 + row] = z;
            }
        }
    __syncthreads();
    if (tid < 128) {
        float m0 = red_m[tid],       z0 = red_z[tid];
        float m1 = red_m[128 + tid], z1 = red_z[128 + tid];
        float mm = fmaxf(m0, m1);
        float zz = z0 * __expf(m0 - mm) + z1 * __expf(m1 - mm);
        g_pm[(b * NPAIR + p) * 128 + tid] = mm;
        g_pz[(b * NPAIR + p) * 128 + tid] = zz;
    }
}

// merge tile partials per (b,t-group), build pos from d1/d2, accumulate loss;
// last block writes the final scalar.
__global__ void k_reduce(float* out) {
    int b = blockIdx.x;
    int k = blockIdx.y;          // t-group 0..3
    int t = k * 128 + threadIdx.x;   // 128 threads
    float loss = 0.f;
    if (t < TV) {
        const int ps_[5] = {0, 4, 7, 9, 10};
        float m = -1e30f, z = 0.f;
        for (int p = ps_[k]; p < ps_[k + 1]; p++) {
            float mp = g_pm[(b * NPAIR + p) * 128 + threadIdx.x];
            float zp = g_pz[(b * NPAIR + p) * 128 + threadIdx.x];
            float mm = fmaxf(m, mp);
            z = z * expf(m - mm) + zp * expf(mp - mm);
            m = mm;
        }
        float s = g_d1[b * NT + t] + g_d2[b * NT + t];
        int cnt = 2;
        if (t >= 1) { s += g_d1[b * NT + t - 1]; cnt++; }
        if (t >= 2) { s += g_d2[b * NT + t - 2]; cnt++; }
        float pscore = s / (float)cnt * TEMP_INV;
        float mm = fmaxf(m, pscore);
        float zz = z * expf(m - mm) + expf(pscore - mm);
        loss = mm + logf(zz) - pscore;
    }
#pragma unroll
    for (int o = 16; o; o >>= 1) loss += __shfl_xor_sync(0xffffffffu, loss, o);
    __shared__ float sm[4];
    if ((threadIdx.x & 31) == 0) sm[threadIdx.x >> 5] = loss;
    __syncthreads();
    if (threadIdx.x == 0) {
        float tot = sm[0] + sm[1] + sm[2] + sm[3];
        atomicAdd(&g_acc, (double)tot);
        __threadfence();
        unsigned v = atomicAdd(&g_done, 1u);
        if (v == NB * 4 - 1) {
            out[0] = (float)(g_acc / (double)((size_t)NB * TV));
            g_done = 0;      // reset for next graph replay
        }
    }
}

// ---------------------------------------------------------------- launch
extern "C" void kernel_launch(void* const* d_in, const int* in_sizes, int n_in,
                              void* d_out, int out_size) {
    const float* h = (const float*)d_in[0];
    (void)in_sizes; (void)n_in; (void)out_size;

    k_norm<<<NB * NT, 128>>>(h);
    k_mma<<<dim3(NPAIR, NB), 256>>>();
    k_reduce<<<dim3(NB, 4), 128>>>((float*)d_out);
}